// round 15
// baseline (speedup 1.0000x reference)
#include <cuda_runtime.h>
#include <cuda_bf16.h>
#include <math.h>
#include <stdint.h>

using bf16 = __nv_bfloat16;

static constexpr int B_   = 8192;
static constexpr int IN_  = 784;
static constexpr int INP_ = 832;     // IN padded to 64 (k-major operands)
static constexpr int INH_ = 896;     // IN padded to 128 (hebb1 A natural pitch)
static constexpr int H1_  = 1024;
static constexpr int H2_  = 1024;
static constexpr int OUT_ = 10;

// ------------------------------ asm helpers -------------------------------
__device__ __forceinline__ uint32_t cvta_smem(const void* p) {
    uint32_t a;
    asm("{ .reg .u64 t; cvta.to.shared.u64 t, %1; cvt.u32.u64 %0, t; }"
        : "=r"(a) : "l"(p));
    return a;
}
__device__ __forceinline__ void cp16(uint32_t dst, const void* src) {
    asm volatile("cp.async.cg.shared.global [%0], [%1], 16;"
                 :: "r"(dst), "l"(src));
}
__device__ __forceinline__ void cp_commit() {
    asm volatile("cp.async.commit_group;" ::: "memory");
}
template <int N>
__device__ __forceinline__ void cp_wait() {
    asm volatile("cp.async.wait_group %0;" :: "n"(N) : "memory");
}
__device__ __forceinline__ void ldm_x4_t(uint32_t* r, uint32_t a) {
    asm volatile("ldmatrix.sync.aligned.m8n8.x4.trans.shared.b16 {%0,%1,%2,%3}, [%4];"
                 : "=r"(r[0]), "=r"(r[1]), "=r"(r[2]), "=r"(r[3]) : "r"(a));
}
__device__ __forceinline__ void mma16816(float* c, const uint32_t a[4],
                                         const uint32_t b[2]) {
    asm volatile(
        "mma.sync.aligned.m16n8k16.row.col.f32.bf16.bf16.f32 "
        "{%0,%1,%2,%3}, {%4,%5,%6,%7}, {%8,%9}, {%0,%1,%2,%3};"
        : "+f"(c[0]), "+f"(c[1]), "+f"(c[2]), "+f"(c[3])
        : "r"(a[0]), "r"(a[1]), "r"(a[2]), "r"(a[3]), "r"(b[0]), "r"(b[1]));
}

// ------------------------------ device scratch -----------------------------
__device__ __align__(16) bf16 g_xh  [(size_t)B_ * INH_];   // natural (B, INH)
__device__ __align__(16) bf16 g_xth [(size_t)INP_ * B_];   // transposed (INP, B)
__device__ __align__(16) bf16 g_xtm [(size_t)INP_ * B_];
__device__ __align__(16) bf16 g_xtl [(size_t)INP_ * B_];
__device__ __align__(16) bf16 g_w1kh[INP_ * H1_];          // k-major (INP, H1)
__device__ __align__(16) bf16 g_w1km[INP_ * H1_];
__device__ __align__(16) bf16 g_w1kl[INP_ * H1_];
__device__ __align__(16) bf16 g_f2kh[H1_ * H2_];           // k-major (H1, H2)
__device__ __align__(16) bf16 g_f2km[H1_ * H2_];
__device__ __align__(16) bf16 g_f2kl[H1_ * H2_];
__device__ __align__(16) bf16 g_ab1h[INP_ * H1_];          // k-major (INP, H1)
__device__ __align__(16) bf16 g_s1t [(size_t)H1_ * B_];    // spikes transposed
__device__ __align__(16) bf16 g_s1bf[(size_t)B_ * H1_];    // spikes natural
__device__ __align__(16) bf16 g_p1h [(size_t)B_ * H1_];
__device__ __align__(16) bf16 g_p2h [(size_t)B_ * H2_];
__device__ float g_Wm3[H2_ * OUT_];
__device__ float g_C1 [(size_t)B_ * H1_];
__device__ float g_m1 [(size_t)B_ * H1_];
__device__ float g_s1 [(size_t)B_ * H1_];
__device__ float g_m2 [(size_t)B_ * H2_];
__device__ float g_s2 [(size_t)B_ * H2_];
__device__ float g_hb1[IN_ * H1_];
__device__ float g_hb2[H1_ * H2_];

// ------------------------------ prep kernels -------------------------------
__device__ __forceinline__ void split3(float v, bf16& h, bf16& m, bf16& l) {
    h = __float2bfloat16(v);
    float r = v - __bfloat162float(h);
    m = __float2bfloat16(r);
    l = __float2bfloat16(r - __bfloat162float(m));
}

__global__ void zero_hebb() {
    int idx = blockIdx.x * blockDim.x + threadIdx.x;
    if (idx < IN_ * H1_) g_hb1[idx] = 0.0f;
    if (idx < H1_ * H2_) g_hb2[idx] = 0.0f;
}

__global__ void split_x(const float* __restrict__ x) {
    size_t idx = (size_t)blockIdx.x * blockDim.x + threadIdx.x;
    if (idx >= (size_t)B_ * INH_) return;
    int m = (int)(idx / INH_), k = (int)(idx % INH_);
    float v = (k < IN_) ? x[(size_t)m * IN_ + k] : 0.0f;
    g_xh[idx] = __float2bfloat16(v);
}

// tiled transpose + 3-split of x -> (INP, B)
__global__ void split_xt(const float* __restrict__ x) {
    __shared__ float t[32][33];
    const int kb = blockIdx.x * 32, mb = blockIdx.y * 32;
#pragma unroll
    for (int r = 0; r < 32; r += 8) {
        int m = mb + threadIdx.y + r, k = kb + threadIdx.x;
        t[threadIdx.y + r][threadIdx.x] =
            (k < IN_) ? x[(size_t)m * IN_ + k] : 0.0f;
    }
    __syncthreads();
#pragma unroll
    for (int r = 0; r < 32; r += 8) {
        int k = kb + threadIdx.y + r, m = mb + threadIdx.x;
        float v = t[threadIdx.x][threadIdx.y + r];
        size_t o = (size_t)k * B_ + m;
        split3(v, g_xth[o], g_xtm[o], g_xtl[o]);
    }
}

__global__ void prep_w1k(const float* __restrict__ fc1, const float* __restrict__ mask0) {
    int idx = blockIdx.x * blockDim.x + threadIdx.x;
    if (idx >= INP_ * H1_) return;
    int k = idx / H1_, n = idx % H1_;
    float v = (k < IN_) ? fc1[n * IN_ + k] * mask0[k * H1_ + n] : 0.0f;
    split3(v, g_w1kh[idx], g_w1km[idx], g_w1kl[idx]);
}

__global__ void prep_f2k(const float* __restrict__ fc2, const float* __restrict__ mask1,
                         const float* __restrict__ alpha2) {
    int idx = blockIdx.x * blockDim.x + threadIdx.x;
    if (idx >= H1_ * H2_) return;
    int k = idx / H2_, n = idx % H2_;
    float v = fmaf(alpha2[0], g_hb2[idx], fc2[n * H1_ + k] * mask1[idx]);
    split3(v, g_f2kh[idx], g_f2km[idx], g_f2kl[idx]);
}

__global__ void prep_ab1(const float* __restrict__ alpha1) {
    int idx = blockIdx.x * blockDim.x + threadIdx.x;
    if (idx >= INP_ * H1_) return;
    int k = idx / H1_, n = idx % H1_;
    float v = (k < IN_) ? alpha1[0] * g_hb1[k * H1_ + n] : 0.0f;
    g_ab1h[idx] = __float2bfloat16(v);
}

__global__ void prep_w3(const float* __restrict__ fc3, const float* __restrict__ mask2) {
    int idx = blockIdx.x * blockDim.x + threadIdx.x;
    if (idx >= H2_ * OUT_) return;
    int k = idx / OUT_, n = idx - k * OUT_;
    g_Wm3[idx] = fc3[n * H2_ + k] * mask2[idx];
}

// ---------------------------------------------------------------------------
// Forward HMMA GEMM — chunk-outer / product-inner (R14 traffic structure)
// with promotion PER A-SPLIT: RZ chains <= 3 (bias law: chain 2 -> 7.2e-4,
// 4 -> 8.2e-4, 6 -> 9.7e-4, 12 -> 1.03e-3; chain <=3 restores pass margin).
// Tile 128x64, 256 thr, 2 CTA/SM, 2-stage cp.async, dynamic smem.
// EP 1: st = acc (C1out = acc); EP 2: st = d*(C1in + acc); EP 3: st = d*acc
// ---------------------------------------------------------------------------
template <int PSET, int EP, bool POST, bool FIRST, bool SPKT>
__global__ void __launch_bounds__(256, 2)
tcf(const bf16* __restrict__ A0, const bf16* __restrict__ A1,
    const bf16* __restrict__ A2,
    const bf16* __restrict__ B0, const bf16* __restrict__ B1,
    const bf16* __restrict__ B2,
    int Kpad, float dscale, const float* __restrict__ eta,
    const float* __restrict__ C1in, float* __restrict__ C1out,
    float* __restrict__ memA, float* __restrict__ spkA,
    bf16* __restrict__ postH, bf16* __restrict__ spkBf,
    bf16* __restrict__ spkT) {
    constexpr int NA = (PSET == 0) ? 3 : 1;
    constexpr int NB = (PSET == 1) ? 1 : 3;
    constexpr int CNTa[3] = {NB, (PSET == 0) ? 2 : 0, (PSET == 0) ? 1 : 0};
    constexpr uint32_t ATILE = 32 * 136 * 2;   // 8704 B
    constexpr uint32_t BTILE = 32 * 72 * 2;    // 4608 B
    constexpr uint32_t STAGE = NA * ATILE + NB * BTILE;

    extern __shared__ __align__(16) bf16 dyn[];
    const uint32_t smemBase = cvta_smem(&dyn[0]);

    const int tid = threadIdx.x, lane = tid & 31, wid = tid >> 5;
    const int wm = wid & 3, wn = wid >> 2;        // 4 x 2 warps (m32 x n32)
    const int bn = blockIdx.x, bm = blockIdx.y;
    const int KC = Kpad >> 5;

    const bf16* Ap[3] = {A0, A1, A2};
    const bf16* Bp[3] = {B0, B1, B2};

    const int lr = tid >> 3;          // 0..31 (k row within chunk)
    const int lc = tid & 7;           // col group

    float acc[2][4][4];               // mma accumulator (chains <= 3 RZ adds)
    float accM[2][4][4];              // promoted IEEE fp32 accumulator
#pragma unroll
    for (int i = 0; i < 2; ++i)
#pragma unroll
        for (int j = 0; j < 4; ++j)
#pragma unroll
            for (int q = 0; q < 4; ++q) { acc[i][j][q] = 0.0f; accM[i][j][q] = 0.0f; }

    auto issue = [&](int c, int s) {
        const uint32_t base = smemBase + (uint32_t)s * STAGE;
#pragma unroll
        for (int a = 0; a < NA; ++a) {
            const bf16* ag = Ap[a] + (size_t)(c * 32 + lr) * B_ + bm * 128 + lc * 16;
            uint32_t off = base + a * ATILE + (uint32_t)(lr * 136 + lc * 16) * 2;
            cp16(off, ag);
            cp16(off + 16, ag + 8);
        }
#pragma unroll
        for (int b = 0; b < NB; ++b) {
            const bf16* bg = Bp[b] + (size_t)(c * 32 + lr) * 1024 + bn * 64 + lc * 8;
            uint32_t off = base + NA * ATILE + b * BTILE + (uint32_t)(lr * 72 + lc * 8) * 2;
            cp16(off, bg);
        }
        cp_commit();
    };

    issue(0, 0);
    issue(1, 1);
    int s = 0;
    for (int c = 0; c < KC; ++c) {
        if (c + 1 < KC) cp_wait<1>(); else cp_wait<0>();
        __syncthreads();
        const uint32_t base = smemBase + (uint32_t)s * STAGE;
        const uint32_t bBb = base + NA * ATILE;
#pragma unroll
        for (int kk = 0; kk < 2; ++kk) {
            // resident B fragments for all NB splits
            uint32_t bfr[NB][4][2];
#pragma unroll
            for (int b = 0; b < NB; ++b) {
#pragma unroll
                for (int jj = 0; jj < 2; ++jj) {
                    uint32_t r[4];
                    int krow = kk * 16 + ((lane >> 3) & 1) * 8 + (lane & 7);
                    int ncol = wn * 32 + jj * 16 + ((lane >> 4) & 1) * 8;
                    ldm_x4_t(r, bBb + b * BTILE + (uint32_t)(krow * 72 + ncol) * 2);
                    bfr[b][jj * 2][0] = r[0]; bfr[b][jj * 2][1] = r[1];
                    bfr[b][jj * 2 + 1][0] = r[2]; bfr[b][jj * 2 + 1][1] = r[3];
                }
            }
            // per A split: fragments once, its B partners, then PROMOTE
#pragma unroll
            for (int a = 0; a < NA; ++a) {
                uint32_t af[2][4];
#pragma unroll
                for (int i = 0; i < 2; ++i) {
                    int krow = kk * 16 + ((lane >> 4) & 1) * 8 + (lane & 7);
                    int mcol = wm * 32 + i * 16 + ((lane >> 3) & 1) * 8;
                    ldm_x4_t(af[i], base + a * ATILE + (uint32_t)(krow * 136 + mcol) * 2);
                }
#pragma unroll
                for (int j = 0; j < CNTa[a]; ++j)
#pragma unroll
                    for (int i = 0; i < 2; ++i)
#pragma unroll
                        for (int nt = 0; nt < 4; ++nt)
                            mma16816(acc[i][nt], af[i], bfr[j][nt]);
                // ---- promotion per A split: IEEE fp32 add, chains <= 3 ----
#pragma unroll
                for (int i = 0; i < 2; ++i)
#pragma unroll
                    for (int j = 0; j < 4; ++j)
#pragma unroll
                        for (int q = 0; q < 4; ++q) {
                            accM[i][j][q] += acc[i][j][q];
                            acc[i][j][q] = 0.0f;
                        }
            }
        }
        __syncthreads();
        if (c + 2 < KC) issue(c + 2, s);
        s ^= 1;
    }

    // -------- fused SNN epilogue (proven mapping + proven math) --------
    const int mbase = bm * 128 + wm * 32;
    const int nbase = bn * 64 + wn * 32;
#pragma unroll
    for (int i = 0; i < 2; ++i) {
#pragma unroll
        for (int h = 0; h < 2; ++h) {
            const int m = mbase + i * 16 + (lane >> 2) + h * 8;
            const size_t roff = (size_t)m * 1024;
#pragma unroll
            for (int j = 0; j < 4; ++j) {
                const int n = nbase + j * 8 + (lane & 3) * 2;
                const size_t idx = roff + n;
                float c0 = accM[i][j][h * 2 + 0];
                float c1 = accM[i][j][h * 2 + 1];
                float st0, st1;
                if (EP == 1) { st0 = c0; st1 = c1; }
                else if (EP == 2) {
                    float2 cv = *reinterpret_cast<const float2*>(C1in + idx);
                    st0 = dscale * (cv.x + c0);
                    st1 = dscale * (cv.y + c1);
                } else { st0 = dscale * c0; st1 = dscale * c1; }
                float m0v, m1v;
                if (FIRST) { m0v = st0; m1v = st1; }
                else {
                    float2 mv = *reinterpret_cast<const float2*>(memA + idx);
                    float2 sv = *reinterpret_cast<const float2*>(spkA + idx);
                    m0v = (mv.x - sv.x * 0.5f) * 0.8f + st0;
                    m1v = (mv.y - sv.y * 0.5f) * 0.8f + st1;
                }
                float sp0 = ((m0v - 0.5f) > 0.0f) ? 1.0f : 0.0f;
                float sp1 = ((m1v - 0.5f) > 0.0f) ? 1.0f : 0.0f;
                *reinterpret_cast<float2*>(memA + idx) = make_float2(m0v, m1v);
                *reinterpret_cast<float2*>(spkA + idx) = make_float2(sp0, sp1);
                if (EP == 1)
                    *reinterpret_cast<float2*>(C1out + idx) = make_float2(c0, c1);
                if (POST) {
                    float2 ev = *reinterpret_cast<const float2*>(eta + n);
                    float p0 = tanhf(2.0f * m0v - ev.x);
                    float p1 = tanhf(2.0f * m1v - ev.y);
                    __nv_bfloat162 hv;
                    hv.x = __float2bfloat16(p0);
                    hv.y = __float2bfloat16(p1);
                    *reinterpret_cast<__nv_bfloat162*>(postH + idx) = hv;
                }
                if (SPKT) {
                    __nv_bfloat162 sv2;
                    sv2.x = __float2bfloat16(sp0);
                    sv2.y = __float2bfloat16(sp1);
                    *reinterpret_cast<__nv_bfloat162*>(spkBf + idx) = sv2;
                    spkT[(size_t)n * B_ + m]       = sv2.x;
                    spkT[(size_t)(n + 1) * B_ + m] = sv2.y;
                }
            }
        }
    }
}

// ---------------------------------------------------------------------------
// Hebb HMMA GEMM — upgraded to 128x64 tile using the PROVEN tcf mainloop
// fragment formulas (single product; full-K RZ accumulation is safe because
// hebb enters mem attenuated ~1e-3 — validated across 7 passing rounds).
// Hb(M x 1024) = 0.8*Hb + (1-mask)*beta[m]*(d/8192)*(A^T @ P)
// A: (8192, Mpitch) bf16 k-major, zero-padded so bm*128+127 < Mpitch.
// ---------------------------------------------------------------------------
__global__ void __launch_bounds__(256)
tc_hebb(const bf16* __restrict__ A, int Mpitch, int M,
        const bf16* __restrict__ P,
        float* __restrict__ Hb, const float* __restrict__ mask,
        const float* __restrict__ beta, float dscale) {
    __shared__ __align__(16) bf16 sA[3][32 * 136];
    __shared__ __align__(16) bf16 sP[3][32 * 72];
    const int tid = threadIdx.x, lane = tid & 31, wid = tid >> 5;
    const int wm = wid & 3, wn = wid >> 2;        // 4 x 2 warps (m32 x n32)
    const int m0b = blockIdx.y * 128, n0b = blockIdx.x * 64;
    const uint32_t aB0 = cvta_smem(&sA[0][0]);
    const uint32_t pB0 = cvta_smem(&sP[0][0]);
    constexpr uint32_t STGA = 32 * 136 * 2;
    constexpr uint32_t STGP = 32 * 72 * 2;

    const int lr = tid >> 3, lc = tid & 7;

    float acc[2][4][4];
#pragma unroll
    for (int i = 0; i < 2; ++i)
#pragma unroll
        for (int j = 0; j < 4; ++j)
#pragma unroll
            for (int q = 0; q < 4; ++q) acc[i][j][q] = 0.0f;

    constexpr int V = 8192 / 32;

    auto issue = [&](int c, int s) {
        const bf16* ag = A + (size_t)(c * 32 + lr) * Mpitch + m0b + lc * 16;
        const bf16* pg = P + (size_t)(c * 32 + lr) * 1024 + n0b + lc * 8;
        uint32_t offA = (uint32_t)(lr * 136 + lc * 16) * 2 + (uint32_t)s * STGA;
        uint32_t offP = (uint32_t)(lr * 72 + lc * 8) * 2 + (uint32_t)s * STGP;
        cp16(aB0 + offA, ag);
        cp16(aB0 + offA + 16, ag + 8);
        cp16(pB0 + offP, pg);
        cp_commit();
    };

    issue(0, 0);
    issue(1, 1);
    issue(2, 2);
    int s = 0;
    for (int v = 0; v < V; ++v) {
        if (v + 3 <= V) cp_wait<2>();
        else if (v + 2 == V) cp_wait<1>();
        else cp_wait<0>();
        __syncthreads();
        const uint32_t aB = aB0 + (uint32_t)s * STGA;
        const uint32_t pB = pB0 + (uint32_t)s * STGP;
#pragma unroll
        for (int kk = 0; kk < 2; ++kk) {
            uint32_t af[2][4];
#pragma unroll
            for (int i = 0; i < 2; ++i) {
                int krow = kk * 16 + ((lane >> 4) & 1) * 8 + (lane & 7);
                int mcol = wm * 32 + i * 16 + ((lane >> 3) & 1) * 8;
                ldm_x4_t(af[i], aB + (uint32_t)(krow * 136 + mcol) * 2);
            }
            uint32_t bf_[4][2];
#pragma unroll
            for (int jj = 0; jj < 2; ++jj) {
                uint32_t r[4];
                int krow = kk * 16 + ((lane >> 3) & 1) * 8 + (lane & 7);
                int ncol = wn * 32 + jj * 16 + ((lane >> 4) & 1) * 8;
                ldm_x4_t(r, pB + (uint32_t)(krow * 72 + ncol) * 2);
                bf_[jj * 2][0] = r[0]; bf_[jj * 2][1] = r[1];
                bf_[jj * 2 + 1][0] = r[2]; bf_[jj * 2 + 1][1] = r[3];
            }
#pragma unroll
            for (int i = 0; i < 2; ++i)
#pragma unroll
                for (int j = 0; j < 4; ++j)
                    mma16816(acc[i][j], af[i], bf_[j]);
        }
        __syncthreads();
        if (v + 3 < V) issue(v + 3, s);
        s = (s == 2) ? 0 : s + 1;
    }

    const float inv = dscale * (1.0f / 8192.0f);
#pragma unroll
    for (int i = 0; i < 2; ++i) {
#pragma unroll
        for (int h = 0; h < 2; ++h) {
            const int m = m0b + wm * 32 + i * 16 + (lane >> 2) + h * 8;
            if (m < M) {
                const float bs = beta[m] * inv;
                const size_t roff = (size_t)m * 1024;
#pragma unroll
                for (int j = 0; j < 4; ++j) {
                    const int n = n0b + wn * 32 + j * 8 + (lane & 3) * 2;
                    const size_t idx = roff + n;
                    float2 hb = *reinterpret_cast<const float2*>(Hb + idx);
                    float2 mk = *reinterpret_cast<const float2*>(mask + idx);
                    hb.x = 0.8f * hb.x + (1.0f - mk.x) * bs * acc[i][j][h * 2 + 0];
                    hb.y = 0.8f * hb.y + (1.0f - mk.y) * bs * acc[i][j][h * 2 + 1];
                    *reinterpret_cast<float2*>(Hb + idx) = hb;
                }
            }
        }
    }
}

// ---------------------------------------------------------------------------
// Output GEMM: out(8192 x 10) = m2 @ Wm3   (fp32 SIMT, proven)
// ---------------------------------------------------------------------------
__global__ void __launch_bounds__(256)
out_gemm(const float* __restrict__ m2, const float* __restrict__ Wm3,
         float* __restrict__ out) {
    __shared__ float sW[H2_ * OUT_];
    const int tid = threadIdx.x;
    for (int i = tid; i < H2_ * OUT_; i += blockDim.x) sW[i] = Wm3[i];
    __syncthreads();

    const int warp = tid >> 5, lane = tid & 31;
    const int b = blockIdx.x * 8 + warp;
    const float* row = m2 + (size_t)b * H2_;

    float acc[OUT_];
#pragma unroll
    for (int j = 0; j < OUT_; j++) acc[j] = 0.0f;
    for (int k = lane; k < H2_; k += 32) {
        float v = row[k];
#pragma unroll
        for (int j = 0; j < OUT_; j++) acc[j] = fmaf(v, sW[k * OUT_ + j], acc[j]);
    }
#pragma unroll
    for (int j = 0; j < OUT_; j++) {
        float sv = acc[j];
#pragma unroll
        for (int o = 16; o > 0; o >>= 1) sv += __shfl_xor_sync(0xffffffffu, sv, o);
        if (lane == 0) out[(size_t)b * OUT_ + j] = sv;
    }
}

// ---------------------------------------------------------------------------
extern "C" void kernel_launch(void* const* d_in, const int* in_sizes, int n_in,
                              void* d_out, int out_size) {
    const float* x      = (const float*)d_in[0];
    const float* mask0  = (const float*)d_in[1];
    const float* mask1  = (const float*)d_in[2];
    const float* mask2  = (const float*)d_in[3];
    const float* fc1    = (const float*)d_in[4];
    const float* fc2    = (const float*)d_in[5];
    const float* fc3    = (const float*)d_in[6];
    const float* alpha1 = (const float*)d_in[7];
    const float* alpha2 = (const float*)d_in[8];
    const float* beta1  = (const float*)d_in[9];
    const float* beta2  = (const float*)d_in[10];
    const float* eta1   = (const float*)d_in[11];
    const float* eta2   = (const float*)d_in[12];
    float* out = (float*)d_out;

    bf16 *xh, *xth, *xtm, *xtl, *w1kh, *w1km, *w1kl;
    bf16 *f2kh, *f2km, *f2kl, *ab1h, *s1t, *s1bf, *p1h, *p2h;
    float *Wm3, *C1, *m1, *s1, *m2, *s2, *hb1, *hb2;
    cudaGetSymbolAddress((void**)&xh,   g_xh);
    cudaGetSymbolAddress((void**)&xth,  g_xth);
    cudaGetSymbolAddress((void**)&xtm,  g_xtm);
    cudaGetSymbolAddress((void**)&xtl,  g_xtl);
    cudaGetSymbolAddress((void**)&w1kh, g_w1kh);
    cudaGetSymbolAddress((void**)&w1km, g_w1km);
    cudaGetSymbolAddress((void**)&w1kl, g_w1kl);
    cudaGetSymbolAddress((void**)&f2kh, g_f2kh);
    cudaGetSymbolAddress((void**)&f2km, g_f2km);
    cudaGetSymbolAddress((void**)&f2kl, g_f2kl);
    cudaGetSymbolAddress((void**)&ab1h, g_ab1h);
    cudaGetSymbolAddress((void**)&s1t,  g_s1t);
    cudaGetSymbolAddress((void**)&s1bf, g_s1bf);
    cudaGetSymbolAddress((void**)&p1h,  g_p1h);
    cudaGetSymbolAddress((void**)&p2h,  g_p2h);
    cudaGetSymbolAddress((void**)&Wm3,  g_Wm3);
    cudaGetSymbolAddress((void**)&C1,   g_C1);
    cudaGetSymbolAddress((void**)&m1,   g_m1);
    cudaGetSymbolAddress((void**)&s1,   g_s1);
    cudaGetSymbolAddress((void**)&m2,   g_m2);
    cudaGetSymbolAddress((void**)&s2,   g_s2);
    cudaGetSymbolAddress((void**)&hb1,  g_hb1);
    cudaGetSymbolAddress((void**)&hb2,  g_hb2);

    const float d0 = 1.0f;
    const float d1 = 0.98019867330675525f;   // float32(exp(-1/50))
    const float d2 = 0.96078943915232320f;   // float32(exp(-2/50))

    // dynamic smem sizes per PSET (2 stages)
    const int DSM0 = 2 * (3 * 8704 + 3 * 4608);   // 79872
    const int DSM1 = 2 * (1 * 8704 + 1 * 4608);   // 26624
    const int DSM2 = 2 * (1 * 8704 + 3 * 4608);   // 45056
    cudaFuncSetAttribute(tcf<0, 1, true,  true,  true >, cudaFuncAttributeMaxDynamicSharedMemorySize, DSM0);
    cudaFuncSetAttribute(tcf<2, 3, true,  true,  false>, cudaFuncAttributeMaxDynamicSharedMemorySize, DSM2);
    cudaFuncSetAttribute(tcf<1, 2, true,  false, true >, cudaFuncAttributeMaxDynamicSharedMemorySize, DSM1);
    cudaFuncSetAttribute(tcf<2, 3, true,  false, false>, cudaFuncAttributeMaxDynamicSharedMemorySize, DSM2);
    cudaFuncSetAttribute(tcf<1, 2, false, false, true >, cudaFuncAttributeMaxDynamicSharedMemorySize, DSM1);
    cudaFuncSetAttribute(tcf<2, 3, false, false, false>, cudaFuncAttributeMaxDynamicSharedMemorySize, DSM2);

    // ---- prep (minimum before first GEMM; rest deferred) ----
    zero_hebb<<<(H1_ * H2_ + 255) / 256, 256>>>();
    split_x<<<(int)(((size_t)B_ * INH_ + 255) / 256), 256>>>(x);
    split_xt<<<dim3(INP_ / 32, B_ / 32), dim3(32, 8)>>>(x);
    prep_w1k<<<(INP_ * H1_ + 255) / 256, 256>>>(fc1, mask0);

    dim3 gF(16, 64);       // forward 128x64 tiles over (8192, 1024)
    dim3 gH1(16, 7);       // hebb1 128x64 tiles over (784->896, 1024)
    dim3 gH2(16, 8);       // hebb2 128x64 tiles over (1024, 1024)

    // ---- step 0 ----
    tcf<0, 1, true, true, true><<<gF, 256, DSM0>>>(
        xth, xtm, xtl, w1kh, w1km, w1kl, INP_, d0, eta1,
        nullptr, C1, m1, s1, p1h, s1bf, s1t);
    tc_hebb<<<gH1, 256>>>(xh, INH_, IN_, p1h, hb1, mask0, beta1, d0);
    prep_f2k<<<(H1_ * H2_ + 255) / 256, 256>>>(fc2, mask1, alpha2);  // hb2 == 0
    tcf<2, 3, true, true, false><<<gF, 256, DSM2>>>(
        s1t, nullptr, nullptr, f2kh, f2km, f2kl, H1_, d0, eta2,
        nullptr, nullptr, m2, s2, p2h, nullptr, nullptr);
    tc_hebb<<<gH2, 256>>>(s1bf, H1_, H1_, p2h, hb2, mask1, beta2, d0);

    // ---- step 1 ----
    prep_ab1<<<(INP_ * H1_ + 255) / 256, 256>>>(alpha1);
    tcf<1, 2, true, false, true><<<gF, 256, DSM1>>>(
        xth, nullptr, nullptr, ab1h, nullptr, nullptr, INP_, d1, eta1,
        C1, nullptr, m1, s1, p1h, s1bf, s1t);
    tc_hebb<<<gH1, 256>>>(xh, INH_, IN_, p1h, hb1, mask0, beta1, d1);
    prep_f2k<<<(H1_ * H2_ + 255) / 256, 256>>>(fc2, mask1, alpha2);
    tcf<2, 3, true, false, false><<<gF, 256, DSM2>>>(
        s1t, nullptr, nullptr, f2kh, f2km, f2kl, H1_, d1, eta2,
        nullptr, nullptr, m2, s2, p2h, nullptr, nullptr);
    tc_hebb<<<gH2, 256>>>(s1bf, H1_, H1_, p2h, hb2, mask1, beta2, d1);

    // ---- step 2 (final hebb updates skipped: never consumed) ----
    prep_ab1<<<(INP_ * H1_ + 255) / 256, 256>>>(alpha1);
    tcf<1, 2, false, false, true><<<gF, 256, DSM1>>>(
        xth, nullptr, nullptr, ab1h, nullptr, nullptr, INP_, d2, eta1,
        C1, nullptr, m1, s1, nullptr, s1bf, s1t);
    prep_f2k<<<(H1_ * H2_ + 255) / 256, 256>>>(fc2, mask1, alpha2);
    tcf<2, 3, false, false, false><<<gF, 256, DSM2>>>(
        s1t, nullptr, nullptr, f2kh, f2km, f2kl, H1_, d2, eta2,
        nullptr, nullptr, m2, s2, nullptr, nullptr, nullptr);

    // ---- output ----
    prep_w3<<<(H2_ * OUT_ + 255) / 256, 256>>>(fc3, mask2);
    out_gemm<<<B_ / 8, 256>>>(m2, Wm3, out);
}

// round 16
// speedup vs baseline: 1.0112x; 1.0112x over previous
#include <cuda_runtime.h>
#include <cuda_bf16.h>
#include <math.h>
#include <stdint.h>

using bf16 = __nv_bfloat16;

static constexpr int B_   = 8192;
static constexpr int IN_  = 784;
static constexpr int INP_ = 832;     // IN padded to multiple of 64
static constexpr int H1_  = 1024;
static constexpr int H2_  = 1024;
static constexpr int OUT_ = 10;

// ------------------------------ asm helpers -------------------------------
__device__ __forceinline__ uint32_t cvta_smem(const void* p) {
    uint32_t a;
    asm("{ .reg .u64 t; cvta.to.shared.u64 t, %1; cvt.u32.u64 %0, t; }"
        : "=r"(a) : "l"(p));
    return a;
}
__device__ __forceinline__ void cp16(uint32_t dst, const void* src) {
    asm volatile("cp.async.cg.shared.global [%0], [%1], 16;"
                 :: "r"(dst), "l"(src));
}
__device__ __forceinline__ void cp_commit() {
    asm volatile("cp.async.commit_group;" ::: "memory");
}
template <int N>
__device__ __forceinline__ void cp_wait() {
    asm volatile("cp.async.wait_group %0;" :: "n"(N) : "memory");
}
__device__ __forceinline__ void ldm_x4_t(uint32_t* r, uint32_t a) {
    asm volatile("ldmatrix.sync.aligned.m8n8.x4.trans.shared.b16 {%0,%1,%2,%3}, [%4];"
                 : "=r"(r[0]), "=r"(r[1]), "=r"(r[2]), "=r"(r[3]) : "r"(a));
}
__device__ __forceinline__ void mma16816(float* c, const uint32_t a[4],
                                         const uint32_t b[2]) {
    asm volatile(
        "mma.sync.aligned.m16n8k16.row.col.f32.bf16.bf16.f32 "
        "{%0,%1,%2,%3}, {%4,%5,%6,%7}, {%8,%9}, {%0,%1,%2,%3};"
        : "+f"(c[0]), "+f"(c[1]), "+f"(c[2]), "+f"(c[3])
        : "r"(a[0]), "r"(a[1]), "r"(a[2]), "r"(a[3]), "r"(b[0]), "r"(b[1]));
}

// ------------------------------ device scratch -----------------------------
__device__ __align__(16) bf16 g_xh  [(size_t)B_ * INP_];   // natural (B, INP)
__device__ __align__(16) bf16 g_xth [(size_t)INP_ * B_];   // transposed (INP, B)
__device__ __align__(16) bf16 g_xtm [(size_t)INP_ * B_];
__device__ __align__(16) bf16 g_xtl [(size_t)INP_ * B_];
__device__ __align__(16) bf16 g_w1kh[INP_ * H1_];          // k-major (INP, H1)
__device__ __align__(16) bf16 g_w1km[INP_ * H1_];
__device__ __align__(16) bf16 g_w1kl[INP_ * H1_];
__device__ __align__(16) bf16 g_f2kh[H1_ * H2_];           // k-major (H1, H2)
__device__ __align__(16) bf16 g_f2km[H1_ * H2_];
__device__ __align__(16) bf16 g_f2kl[H1_ * H2_];
__device__ __align__(16) bf16 g_ab1h[INP_ * H1_];          // k-major (INP, H1)
__device__ __align__(16) bf16 g_s1t [(size_t)H1_ * B_];    // spikes transposed
__device__ __align__(16) bf16 g_s1bf[(size_t)B_ * H1_];    // spikes natural
__device__ __align__(16) bf16 g_p1h [(size_t)B_ * H1_];
__device__ __align__(16) bf16 g_p2h [(size_t)B_ * H2_];
__device__ float g_Wm3[H2_ * OUT_];
__device__ float g_C1 [(size_t)B_ * H1_];
__device__ float g_m1 [(size_t)B_ * H1_];
__device__ float g_s1 [(size_t)B_ * H1_];
__device__ float g_m2 [(size_t)B_ * H2_];
__device__ float g_s2 [(size_t)B_ * H2_];
__device__ float g_hb1[IN_ * H1_];
__device__ float g_hb2[H1_ * H2_];

// ------------------------------ prep kernels -------------------------------
__device__ __forceinline__ void split3(float v, bf16& h, bf16& m, bf16& l) {
    h = __float2bfloat16(v);
    float r = v - __bfloat162float(h);
    m = __float2bfloat16(r);
    l = __float2bfloat16(r - __bfloat162float(m));
}

__global__ void zero_hebb() {
    int idx = blockIdx.x * blockDim.x + threadIdx.x;
    if (idx < IN_ * H1_) g_hb1[idx] = 0.0f;
    if (idx < H1_ * H2_) g_hb2[idx] = 0.0f;
    // zero ab1 padding rows [IN_, INP_) once (hebb1 epilogue fills rows < IN_)
    if (idx < (INP_ - IN_) * H1_) g_ab1h[IN_ * H1_ + idx] = __float2bfloat16(0.0f);
}

__global__ void split_x(const float* __restrict__ x) {
    size_t idx = (size_t)blockIdx.x * blockDim.x + threadIdx.x;
    if (idx >= (size_t)B_ * INP_) return;
    int m = (int)(idx / INP_), k = (int)(idx % INP_);
    float v = (k < IN_) ? x[(size_t)m * IN_ + k] : 0.0f;
    g_xh[idx] = __float2bfloat16(v);
}

// tiled transpose + 3-split of x -> (INP, B)
__global__ void split_xt(const float* __restrict__ x) {
    __shared__ float t[32][33];
    const int kb = blockIdx.x * 32, mb = blockIdx.y * 32;
#pragma unroll
    for (int r = 0; r < 32; r += 8) {
        int m = mb + threadIdx.y + r, k = kb + threadIdx.x;
        t[threadIdx.y + r][threadIdx.x] =
            (k < IN_) ? x[(size_t)m * IN_ + k] : 0.0f;
    }
    __syncthreads();
#pragma unroll
    for (int r = 0; r < 32; r += 8) {
        int k = kb + threadIdx.y + r, m = mb + threadIdx.x;
        float v = t[threadIdx.x][threadIdx.y + r];
        size_t o = (size_t)k * B_ + m;
        split3(v, g_xth[o], g_xtm[o], g_xtl[o]);
    }
}

__global__ void prep_w1k(const float* __restrict__ fc1, const float* __restrict__ mask0) {
    int idx = blockIdx.x * blockDim.x + threadIdx.x;
    if (idx >= INP_ * H1_) return;
    int k = idx / H1_, n = idx % H1_;
    float v = (k < IN_) ? fc1[n * IN_ + k] * mask0[k * H1_ + n] : 0.0f;
    split3(v, g_w1kh[idx], g_w1km[idx], g_w1kl[idx]);
}

__global__ void prep_f2k(const float* __restrict__ fc2, const float* __restrict__ mask1,
                         const float* __restrict__ alpha2) {
    int idx = blockIdx.x * blockDim.x + threadIdx.x;
    if (idx >= H1_ * H2_) return;
    int k = idx / H2_, n = idx % H2_;
    float v = fmaf(alpha2[0], g_hb2[idx], fc2[n * H1_ + k] * mask1[idx]);
    split3(v, g_f2kh[idx], g_f2km[idx], g_f2kl[idx]);
}

__global__ void prep_w3(const float* __restrict__ fc3, const float* __restrict__ mask2) {
    int idx = blockIdx.x * blockDim.x + threadIdx.x;
    if (idx >= H2_ * OUT_) return;
    int k = idx / OUT_, n = idx - k * OUT_;
    g_Wm3[idx] = fc3[n * H2_ + k] * mask2[idx];
}

// ---------------------------------------------------------------------------
// Forward HMMA GEMM — R14 arithmetic verbatim (chunk-outer/product-inner,
// promotion per 16-k half-chunk). Only pipeline depth changed: PSET0 2-stage,
// PSET1/2 3-stage (no arithmetic change -> bitwise-identical results).
// Tile 128x64, 256 thr, 2 CTA/SM, dynamic smem.
// EP 1: st = acc (C1out = acc); EP 2: st = d*(C1in + acc); EP 3: st = d*acc
// ---------------------------------------------------------------------------
template <int PSET, int EP, bool POST, bool FIRST, bool SPKT>
__global__ void __launch_bounds__(256, 2)
tcf(const bf16* __restrict__ A0, const bf16* __restrict__ A1,
    const bf16* __restrict__ A2,
    const bf16* __restrict__ B0, const bf16* __restrict__ B1,
    const bf16* __restrict__ B2,
    int Kpad, float dscale, const float* __restrict__ eta,
    const float* __restrict__ C1in, float* __restrict__ C1out,
    float* __restrict__ memA, float* __restrict__ spkA,
    bf16* __restrict__ postH, bf16* __restrict__ spkBf,
    bf16* __restrict__ spkT) {
    constexpr int NA = (PSET == 0) ? 3 : 1;
    constexpr int NB = (PSET == 1) ? 1 : 3;
    constexpr int CNTa[3] = {NB, (PSET == 0) ? 2 : 0, (PSET == 0) ? 1 : 0};
    constexpr int ST = (PSET == 0) ? 2 : 3;       // pipeline stages
    constexpr uint32_t ATILE = 32 * 136 * 2;      // 8704 B
    constexpr uint32_t BTILE = 32 * 72 * 2;       // 4608 B
    constexpr uint32_t STAGE = NA * ATILE + NB * BTILE;

    extern __shared__ __align__(16) bf16 dyn[];
    const uint32_t smemBase = cvta_smem(&dyn[0]);

    const int tid = threadIdx.x, lane = tid & 31, wid = tid >> 5;
    const int wm = wid & 3, wn = wid >> 2;        // 4 x 2 warps (m32 x n32)
    const int bn = blockIdx.x, bm = blockIdx.y;
    const int KC = Kpad >> 5;

    const bf16* Ap[3] = {A0, A1, A2};
    const bf16* Bp[3] = {B0, B1, B2};

    const int lr = tid >> 3;          // 0..31 (k row within chunk)
    const int lc = tid & 7;           // col group

    float acc[2][4][4];               // mma accumulator (short RZ chains)
    float accM[2][4][4];              // promoted IEEE fp32 accumulator
#pragma unroll
    for (int i = 0; i < 2; ++i)
#pragma unroll
        for (int j = 0; j < 4; ++j)
#pragma unroll
            for (int q = 0; q < 4; ++q) { acc[i][j][q] = 0.0f; accM[i][j][q] = 0.0f; }

    auto issue = [&](int c, int s) {
        const uint32_t base = smemBase + (uint32_t)s * STAGE;
#pragma unroll
        for (int a = 0; a < NA; ++a) {
            const bf16* ag = Ap[a] + (size_t)(c * 32 + lr) * B_ + bm * 128 + lc * 16;
            uint32_t off = base + a * ATILE + (uint32_t)(lr * 136 + lc * 16) * 2;
            cp16(off, ag);
            cp16(off + 16, ag + 8);
        }
#pragma unroll
        for (int b = 0; b < NB; ++b) {
            const bf16* bg = Bp[b] + (size_t)(c * 32 + lr) * 1024 + bn * 64 + lc * 8;
            uint32_t off = base + NA * ATILE + b * BTILE + (uint32_t)(lr * 72 + lc * 8) * 2;
            cp16(off, bg);
        }
        cp_commit();
    };

    issue(0, 0);
    issue(1, 1);
    if (ST == 3) issue(2, 2);
    int s = 0;
    for (int c = 0; c < KC; ++c) {
        if (ST == 2) {
            if (c + 1 < KC) cp_wait<1>(); else cp_wait<0>();
        } else {
            if (c + 2 < KC) cp_wait<2>();
            else if (c + 1 < KC) cp_wait<1>();
            else cp_wait<0>();
        }
        __syncthreads();
        const uint32_t base = smemBase + (uint32_t)s * STAGE;
        const uint32_t bBb = base + NA * ATILE;
#pragma unroll
        for (int kk = 0; kk < 2; ++kk) {
            // resident B fragments for all NB splits
            uint32_t bfr[NB][4][2];
#pragma unroll
            for (int b = 0; b < NB; ++b) {
#pragma unroll
                for (int jj = 0; jj < 2; ++jj) {
                    uint32_t r[4];
                    int krow = kk * 16 + ((lane >> 3) & 1) * 8 + (lane & 7);
                    int ncol = wn * 32 + jj * 16 + ((lane >> 4) & 1) * 8;
                    ldm_x4_t(r, bBb + b * BTILE + (uint32_t)(krow * 72 + ncol) * 2);
                    bfr[b][jj * 2][0] = r[0]; bfr[b][jj * 2][1] = r[1];
                    bfr[b][jj * 2 + 1][0] = r[2]; bfr[b][jj * 2 + 1][1] = r[3];
                }
            }
            // per A split: load fragments once, multiply into all its B partners
#pragma unroll
            for (int a = 0; a < NA; ++a) {
                uint32_t af[2][4];
#pragma unroll
                for (int i = 0; i < 2; ++i) {
                    int krow = kk * 16 + ((lane >> 4) & 1) * 8 + (lane & 7);
                    int mcol = wm * 32 + i * 16 + ((lane >> 3) & 1) * 8;
                    ldm_x4_t(af[i], base + a * ATILE + (uint32_t)(krow * 136 + mcol) * 2);
                }
#pragma unroll
                for (int j = 0; j < CNTa[a]; ++j)
#pragma unroll
                    for (int i = 0; i < 2; ++i)
#pragma unroll
                        for (int nt = 0; nt < 4; ++nt)
                            mma16816(acc[i][nt], af[i], bfr[j][nt]);
            }
            // ---- promotion per 16-k half-chunk (R14 order, bitwise) ----
#pragma unroll
            for (int i = 0; i < 2; ++i)
#pragma unroll
                for (int j = 0; j < 4; ++j)
#pragma unroll
                    for (int q = 0; q < 4; ++q) {
                        accM[i][j][q] += acc[i][j][q];
                        acc[i][j][q] = 0.0f;
                    }
        }
        __syncthreads();
        if (c + ST < KC) issue(c + ST, s);
        s = (s + 1 == ST) ? 0 : s + 1;
    }

    // -------- fused SNN epilogue (proven mapping + proven math) --------
    const int mbase = bm * 128 + wm * 32;
    const int nbase = bn * 64 + wn * 32;
#pragma unroll
    for (int i = 0; i < 2; ++i) {
#pragma unroll
        for (int h = 0; h < 2; ++h) {
            const int m = mbase + i * 16 + (lane >> 2) + h * 8;
            const size_t roff = (size_t)m * 1024;
#pragma unroll
            for (int j = 0; j < 4; ++j) {
                const int n = nbase + j * 8 + (lane & 3) * 2;
                const size_t idx = roff + n;
                float c0 = accM[i][j][h * 2 + 0];
                float c1 = accM[i][j][h * 2 + 1];
                float st0, st1;
                if (EP == 1) { st0 = c0; st1 = c1; }
                else if (EP == 2) {
                    float2 cv = *reinterpret_cast<const float2*>(C1in + idx);
                    st0 = dscale * (cv.x + c0);
                    st1 = dscale * (cv.y + c1);
                } else { st0 = dscale * c0; st1 = dscale * c1; }
                float m0v, m1v;
                if (FIRST) { m0v = st0; m1v = st1; }
                else {
                    float2 mv = *reinterpret_cast<const float2*>(memA + idx);
                    float2 sv = *reinterpret_cast<const float2*>(spkA + idx);
                    m0v = (mv.x - sv.x * 0.5f) * 0.8f + st0;
                    m1v = (mv.y - sv.y * 0.5f) * 0.8f + st1;
                }
                float sp0 = ((m0v - 0.5f) > 0.0f) ? 1.0f : 0.0f;
                float sp1 = ((m1v - 0.5f) > 0.0f) ? 1.0f : 0.0f;
                *reinterpret_cast<float2*>(memA + idx) = make_float2(m0v, m1v);
                *reinterpret_cast<float2*>(spkA + idx) = make_float2(sp0, sp1);
                if (EP == 1)
                    *reinterpret_cast<float2*>(C1out + idx) = make_float2(c0, c1);
                if (POST) {
                    float2 ev = *reinterpret_cast<const float2*>(eta + n);
                    float p0 = tanhf(2.0f * m0v - ev.x);
                    float p1 = tanhf(2.0f * m1v - ev.y);
                    __nv_bfloat162 hv;
                    hv.x = __float2bfloat16(p0);
                    hv.y = __float2bfloat16(p1);
                    *reinterpret_cast<__nv_bfloat162*>(postH + idx) = hv;
                }
                if (SPKT) {
                    __nv_bfloat162 sv2;
                    sv2.x = __float2bfloat16(sp0);
                    sv2.y = __float2bfloat16(sp1);
                    *reinterpret_cast<__nv_bfloat162*>(spkBf + idx) = sv2;
                    spkT[(size_t)n * B_ + m]       = sv2.x;
                    spkT[(size_t)(n + 1) * B_ + m] = sv2.y;
                }
            }
        }
    }
}

// ---------------------------------------------------------------------------
// Hebb HMMA GEMM (R14 proven 64x64 3-stage, arithmetic verbatim).
// Hb(M x 1024) = 0.8*Hb + (1-mask)*beta[m]*(d/8192)*(A^T @ P)
// EMIT_AB1: additionally emit ab1[idx] = bf16(alpha1 * hb_new) — same index
// and same value prep_ab1 computed (bitwise-identical fusion).
// ---------------------------------------------------------------------------
template <bool EMIT_AB1>
__global__ void __launch_bounds__(256)
tc_hebb(const bf16* __restrict__ A, int Mpitch, int M,
        const bf16* __restrict__ P,
        float* __restrict__ Hb, const float* __restrict__ mask,
        const float* __restrict__ beta, float dscale,
        const float* __restrict__ alpha1, bf16* __restrict__ ab1) {
    __shared__ __align__(16) bf16 sA[3][32 * 72];
    __shared__ __align__(16) bf16 sP[3][32 * 72];
    const int tid = threadIdx.x, lane = tid & 31, wid = tid >> 5;
    const int wm = wid & 3, wn = wid >> 2;
    const int m0b = blockIdx.y * 64, n0b = blockIdx.x * 64;
    const uint32_t aB0 = cvta_smem(&sA[0][0]);
    const uint32_t pB0 = cvta_smem(&sP[0][0]);
    constexpr uint32_t STG = 32 * 72 * 2;

    const int srow = tid >> 3, sc = tid & 7;

    float acc[4][4];
#pragma unroll
    for (int j = 0; j < 4; ++j)
#pragma unroll
        for (int q = 0; q < 4; ++q) acc[j][q] = 0.0f;

    constexpr int V = 8192 / 32;

    auto issue = [&](int c, int s) {
        const bf16* ag = A + (size_t)(c * 32 + srow) * Mpitch + m0b + sc * 8;
        const bf16* pg = P + (size_t)(c * 32 + srow) * 1024 + n0b + sc * 8;
        uint32_t off = (uint32_t)(srow * 72 + sc * 8) * 2 + (uint32_t)s * STG;
        cp16(aB0 + off, ag);
        cp16(pB0 + off, pg);
        cp_commit();
    };

    issue(0, 0);
    issue(1, 1);
    issue(2, 2);
    int s = 0;
    for (int v = 0; v < V; ++v) {
        if (v + 3 <= V) cp_wait<2>();
        else if (v + 2 == V) cp_wait<1>();
        else cp_wait<0>();
        __syncthreads();
        const uint32_t aB = aB0 + (uint32_t)s * STG;
        const uint32_t pB = pB0 + (uint32_t)s * STG;
#pragma unroll
        for (int kk = 0; kk < 2; ++kk) {
            uint32_t af[4];
            {
                int krow = kk * 16 + ((lane >> 4) & 1) * 8 + (lane & 7);
                int mcol = wm * 16 + ((lane >> 3) & 1) * 8;
                ldm_x4_t(af, aB + (uint32_t)(krow * 72 + mcol) * 2);
            }
            uint32_t bf_[4][2];
#pragma unroll
            for (int jj = 0; jj < 2; ++jj) {
                uint32_t r[4];
                int krow = kk * 16 + ((lane >> 3) & 1) * 8 + (lane & 7);
                int ncol = wn * 32 + jj * 16 + ((lane >> 4) & 1) * 8;
                ldm_x4_t(r, pB + (uint32_t)(krow * 72 + ncol) * 2);
                bf_[jj * 2][0] = r[0]; bf_[jj * 2][1] = r[1];
                bf_[jj * 2 + 1][0] = r[2]; bf_[jj * 2 + 1][1] = r[3];
            }
#pragma unroll
            for (int j = 0; j < 4; ++j)
                mma16816(acc[j], af, bf_[j]);
        }
        __syncthreads();
        if (v + 3 < V) issue(v + 3, s);
        s = (s == 2) ? 0 : s + 1;
    }

    const float inv = dscale * (1.0f / 8192.0f);
    const float aV = EMIT_AB1 ? alpha1[0] : 0.0f;
#pragma unroll
    for (int h = 0; h < 2; ++h) {
        const int m = m0b + wm * 16 + (lane >> 2) + h * 8;
        if (m < M) {
            const float bs = beta[m] * inv;
            const size_t roff = (size_t)m * 1024;
#pragma unroll
            for (int j = 0; j < 4; ++j) {
                const int n = n0b + wn * 32 + j * 8 + (lane & 3) * 2;
                const size_t idx = roff + n;
                float2 hb = *reinterpret_cast<const float2*>(Hb + idx);
                float2 mk = *reinterpret_cast<const float2*>(mask + idx);
                hb.x = 0.8f * hb.x + (1.0f - mk.x) * bs * acc[j][h * 2 + 0];
                hb.y = 0.8f * hb.y + (1.0f - mk.y) * bs * acc[j][h * 2 + 1];
                *reinterpret_cast<float2*>(Hb + idx) = hb;
                if (EMIT_AB1) {
                    __nv_bfloat162 av;
                    av.x = __float2bfloat16(aV * hb.x);
                    av.y = __float2bfloat16(aV * hb.y);
                    *reinterpret_cast<__nv_bfloat162*>(ab1 + idx) = av;
                }
            }
        }
    }
}

// ---------------------------------------------------------------------------
// Output GEMM: out(8192 x 10) = m2 @ Wm3   (fp32 SIMT, proven)
// ---------------------------------------------------------------------------
__global__ void __launch_bounds__(256)
out_gemm(const float* __restrict__ m2, const float* __restrict__ Wm3,
         float* __restrict__ out) {
    __shared__ float sW[H2_ * OUT_];
    const int tid = threadIdx.x;
    for (int i = tid; i < H2_ * OUT_; i += blockDim.x) sW[i] = Wm3[i];
    __syncthreads();

    const int warp = tid >> 5, lane = tid & 31;
    const int b = blockIdx.x * 8 + warp;
    const float* row = m2 + (size_t)b * H2_;

    float acc[OUT_];
#pragma unroll
    for (int j = 0; j < OUT_; j++) acc[j] = 0.0f;
    for (int k = lane; k < H2_; k += 32) {
        float v = row[k];
#pragma unroll
        for (int j = 0; j < OUT_; j++) acc[j] = fmaf(v, sW[k * OUT_ + j], acc[j]);
    }
#pragma unroll
    for (int j = 0; j < OUT_; j++) {
        float sv = acc[j];
#pragma unroll
        for (int o = 16; o > 0; o >>= 1) sv += __shfl_xor_sync(0xffffffffu, sv, o);
        if (lane == 0) out[(size_t)b * OUT_ + j] = sv;
    }
}

// ---------------------------------------------------------------------------
extern "C" void kernel_launch(void* const* d_in, const int* in_sizes, int n_in,
                              void* d_out, int out_size) {
    const float* x      = (const float*)d_in[0];
    const float* mask0  = (const float*)d_in[1];
    const float* mask1  = (const float*)d_in[2];
    const float* mask2  = (const float*)d_in[3];
    const float* fc1    = (const float*)d_in[4];
    const float* fc2    = (const float*)d_in[5];
    const float* fc3    = (const float*)d_in[6];
    const float* alpha1 = (const float*)d_in[7];
    const float* alpha2 = (const float*)d_in[8];
    const float* beta1  = (const float*)d_in[9];
    const float* beta2  = (const float*)d_in[10];
    const float* eta1   = (const float*)d_in[11];
    const float* eta2   = (const float*)d_in[12];
    float* out = (float*)d_out;

    bf16 *xh, *xth, *xtm, *xtl, *w1kh, *w1km, *w1kl;
    bf16 *f2kh, *f2km, *f2kl, *ab1h, *s1t, *s1bf, *p1h, *p2h;
    float *Wm3, *C1, *m1, *s1, *m2, *s2, *hb1, *hb2;
    cudaGetSymbolAddress((void**)&xh,   g_xh);
    cudaGetSymbolAddress((void**)&xth,  g_xth);
    cudaGetSymbolAddress((void**)&xtm,  g_xtm);
    cudaGetSymbolAddress((void**)&xtl,  g_xtl);
    cudaGetSymbolAddress((void**)&w1kh, g_w1kh);
    cudaGetSymbolAddress((void**)&w1km, g_w1km);
    cudaGetSymbolAddress((void**)&w1kl, g_w1kl);
    cudaGetSymbolAddress((void**)&f2kh, g_f2kh);
    cudaGetSymbolAddress((void**)&f2km, g_f2km);
    cudaGetSymbolAddress((void**)&f2kl, g_f2kl);
    cudaGetSymbolAddress((void**)&ab1h, g_ab1h);
    cudaGetSymbolAddress((void**)&s1t,  g_s1t);
    cudaGetSymbolAddress((void**)&s1bf, g_s1bf);
    cudaGetSymbolAddress((void**)&p1h,  g_p1h);
    cudaGetSymbolAddress((void**)&p2h,  g_p2h);
    cudaGetSymbolAddress((void**)&Wm3,  g_Wm3);
    cudaGetSymbolAddress((void**)&C1,   g_C1);
    cudaGetSymbolAddress((void**)&m1,   g_m1);
    cudaGetSymbolAddress((void**)&s1,   g_s1);
    cudaGetSymbolAddress((void**)&m2,   g_m2);
    cudaGetSymbolAddress((void**)&s2,   g_s2);
    cudaGetSymbolAddress((void**)&hb1,  g_hb1);
    cudaGetSymbolAddress((void**)&hb2,  g_hb2);

    const float d0 = 1.0f;
    const float d1 = 0.98019867330675525f;   // float32(exp(-1/50))
    const float d2 = 0.96078943915232320f;   // float32(exp(-2/50))

    // dynamic smem sizes per PSET
    const int DSM0 = 2 * (3 * 8704 + 3 * 4608);   // 79872 (2-stage)
    const int DSM1 = 3 * (1 * 8704 + 1 * 4608);   // 39936 (3-stage)
    const int DSM2 = 3 * (1 * 8704 + 3 * 4608);   // 67584 (3-stage)
    cudaFuncSetAttribute(tcf<0, 1, true,  true,  true >, cudaFuncAttributeMaxDynamicSharedMemorySize, DSM0);
    cudaFuncSetAttribute(tcf<2, 3, true,  true,  false>, cudaFuncAttributeMaxDynamicSharedMemorySize, DSM2);
    cudaFuncSetAttribute(tcf<1, 2, true,  false, true >, cudaFuncAttributeMaxDynamicSharedMemorySize, DSM1);
    cudaFuncSetAttribute(tcf<2, 3, true,  false, false>, cudaFuncAttributeMaxDynamicSharedMemorySize, DSM2);
    cudaFuncSetAttribute(tcf<1, 2, false, false, true >, cudaFuncAttributeMaxDynamicSharedMemorySize, DSM1);
    cudaFuncSetAttribute(tcf<2, 3, false, false, false>, cudaFuncAttributeMaxDynamicSharedMemorySize, DSM2);

    // ---- prep (minimum before first GEMM; rest deferred) ----
    zero_hebb<<<(H1_ * H2_ + 255) / 256, 256>>>();
    split_x<<<(int)(((size_t)B_ * INP_ + 255) / 256), 256>>>(x);
    split_xt<<<dim3(INP_ / 32, B_ / 32), dim3(32, 8)>>>(x);
    prep_w1k<<<(INP_ * H1_ + 255) / 256, 256>>>(fc1, mask0);

    dim3 gF(16, 64);       // forward 128x64 tiles over (8192, 1024)
    dim3 gH1(16, 13);      // hebb1 64x64 tiles over (784, 1024)
    dim3 gH2(16, 16);      // hebb2 over (1024, 1024)

    // ---- step 0 ----
    tcf<0, 1, true, true, true><<<gF, 256, DSM0>>>(
        xth, xtm, xtl, w1kh, w1km, w1kl, INP_, d0, eta1,
        nullptr, C1, m1, s1, p1h, s1bf, s1t);
    tc_hebb<true><<<gH1, 256>>>(xh, INP_, IN_, p1h, hb1, mask0, beta1, d0,
                                alpha1, ab1h);
    prep_f2k<<<(H1_ * H2_ + 255) / 256, 256>>>(fc2, mask1, alpha2);  // hb2 == 0
    tcf<2, 3, true, true, false><<<gF, 256, DSM2>>>(
        s1t, nullptr, nullptr, f2kh, f2km, f2kl, H1_, d0, eta2,
        nullptr, nullptr, m2, s2, p2h, nullptr, nullptr);
    tc_hebb<false><<<gH2, 256>>>(s1bf, H1_, H1_, p2h, hb2, mask1, beta2, d0,
                                 nullptr, nullptr);

    // ---- step 1 ----
    tcf<1, 2, true, false, true><<<gF, 256, DSM1>>>(
        xth, nullptr, nullptr, ab1h, nullptr, nullptr, INP_, d1, eta1,
        C1, nullptr, m1, s1, p1h, s1bf, s1t);
    tc_hebb<true><<<gH1, 256>>>(xh, INP_, IN_, p1h, hb1, mask0, beta1, d1,
                                alpha1, ab1h);
    prep_f2k<<<(H1_ * H2_ + 255) / 256, 256>>>(fc2, mask1, alpha2);
    tcf<2, 3, true, false, false><<<gF, 256, DSM2>>>(
        s1t, nullptr, nullptr, f2kh, f2km, f2kl, H1_, d1, eta2,
        nullptr, nullptr, m2, s2, p2h, nullptr, nullptr);
    tc_hebb<false><<<gH2, 256>>>(s1bf, H1_, H1_, p2h, hb2, mask1, beta2, d1,
                                 nullptr, nullptr);

    // ---- step 2 (final hebb updates skipped: never consumed) ----
    tcf<1, 2, false, false, true><<<gF, 256, DSM1>>>(
        xth, nullptr, nullptr, ab1h, nullptr, nullptr, INP_, d2, eta1,
        C1, nullptr, m1, s1, nullptr, s1bf, s1t);
    prep_f2k<<<(H1_ * H2_ + 255) / 256, 256>>>(fc2, mask1, alpha2);
    tcf<2, 3, false, false, false><<<gF, 256, DSM2>>>(
        s1t, nullptr, nullptr, f2kh, f2km, f2kl, H1_, d2, eta2,
        nullptr, nullptr, m2, s2, nullptr, nullptr, nullptr);

    // ---- output ----
    prep_w3<<<(H2_ * OUT_ + 255) / 256, 256>>>(fc3, mask2);
    out_gemm<<<B_ / 8, 256>>>(m2, Wm3, out);
}

// round 17
// speedup vs baseline: 1.0859x; 1.0738x over previous
#include <cuda_runtime.h>
#include <cuda_bf16.h>
#include <math.h>
#include <stdint.h>

using bf16 = __nv_bfloat16;

static constexpr int B_   = 8192;
static constexpr int IN_  = 784;
static constexpr int INP_ = 832;     // IN padded to multiple of 64
static constexpr int H1_  = 1024;
static constexpr int H2_  = 1024;
static constexpr int OUT_ = 10;

// ------------------------------ asm helpers -------------------------------
__device__ __forceinline__ uint32_t cvta_smem(const void* p) {
    uint32_t a;
    asm("{ .reg .u64 t; cvta.to.shared.u64 t, %1; cvt.u32.u64 %0, t; }"
        : "=r"(a) : "l"(p));
    return a;
}
__device__ __forceinline__ void cp16(uint32_t dst, const void* src) {
    asm volatile("cp.async.cg.shared.global [%0], [%1], 16;"
                 :: "r"(dst), "l"(src));
}
__device__ __forceinline__ void cp_commit() {
    asm volatile("cp.async.commit_group;" ::: "memory");
}
template <int N>
__device__ __forceinline__ void cp_wait() {
    asm volatile("cp.async.wait_group %0;" :: "n"(N) : "memory");
}
__device__ __forceinline__ void ldm_x4_t(uint32_t* r, uint32_t a) {
    asm volatile("ldmatrix.sync.aligned.m8n8.x4.trans.shared.b16 {%0,%1,%2,%3}, [%4];"
                 : "=r"(r[0]), "=r"(r[1]), "=r"(r[2]), "=r"(r[3]) : "r"(a));
}
__device__ __forceinline__ void mma16816(float* c, const uint32_t a[4],
                                         const uint32_t b[2]) {
    asm volatile(
        "mma.sync.aligned.m16n8k16.row.col.f32.bf16.bf16.f32 "
        "{%0,%1,%2,%3}, {%4,%5,%6,%7}, {%8,%9}, {%0,%1,%2,%3};"
        : "+f"(c[0]), "+f"(c[1]), "+f"(c[2]), "+f"(c[3])
        : "r"(a[0]), "r"(a[1]), "r"(a[2]), "r"(a[3]), "r"(b[0]), "r"(b[1]));
}

// ------------------------------ device scratch -----------------------------
__device__ __align__(16) bf16 g_xh  [(size_t)B_ * INP_];   // natural (B, INP)
__device__ __align__(16) bf16 g_xth [(size_t)INP_ * B_];   // transposed (INP, B)
__device__ __align__(16) bf16 g_xtm [(size_t)INP_ * B_];
__device__ __align__(16) bf16 g_xtl [(size_t)INP_ * B_];
__device__ __align__(16) bf16 g_w1kh[INP_ * H1_];          // k-major (INP, H1)
__device__ __align__(16) bf16 g_w1km[INP_ * H1_];
__device__ __align__(16) bf16 g_w1kl[INP_ * H1_];
__device__ __align__(16) bf16 g_f2kh[H1_ * H2_];           // k-major (H1, H2)
__device__ __align__(16) bf16 g_f2km[H1_ * H2_];
__device__ __align__(16) bf16 g_f2kl[H1_ * H2_];
__device__ __align__(16) bf16 g_ab1h[INP_ * H1_];          // k-major (INP, H1)
__device__ __align__(16) bf16 g_s1t [(size_t)H1_ * B_];    // spikes transposed
__device__ __align__(16) bf16 g_s1bf[(size_t)B_ * H1_];    // spikes natural
__device__ __align__(16) bf16 g_p1h [(size_t)B_ * H1_];
__device__ __align__(16) bf16 g_p2h [(size_t)B_ * H2_];
__device__ float g_Wm3[H2_ * OUT_];
__device__ float g_C1 [(size_t)B_ * H1_];
__device__ float g_m1 [(size_t)B_ * H1_];
__device__ float g_s1 [(size_t)B_ * H1_];
__device__ float g_m2 [(size_t)B_ * H2_];
__device__ float g_s2 [(size_t)B_ * H2_];
__device__ float g_hb1[IN_ * H1_];
__device__ float g_hb2[H1_ * H2_];

// ------------------------------ prep kernels -------------------------------
__device__ __forceinline__ void split3(float v, bf16& h, bf16& m, bf16& l) {
    h = __float2bfloat16(v);
    float r = v - __bfloat162float(h);
    m = __float2bfloat16(r);
    l = __float2bfloat16(r - __bfloat162float(m));
}

__global__ void zero_hebb() {
    int idx = blockIdx.x * blockDim.x + threadIdx.x;
    if (idx < IN_ * H1_) g_hb1[idx] = 0.0f;
    if (idx < H1_ * H2_) g_hb2[idx] = 0.0f;
    if (idx < (INP_ - IN_) * H1_) g_ab1h[IN_ * H1_ + idx] = __float2bfloat16(0.0f);
}

__global__ void split_x(const float* __restrict__ x) {
    size_t idx = (size_t)blockIdx.x * blockDim.x + threadIdx.x;
    if (idx >= (size_t)B_ * INP_) return;
    int m = (int)(idx / INP_), k = (int)(idx % INP_);
    float v = (k < IN_) ? x[(size_t)m * IN_ + k] : 0.0f;
    g_xh[idx] = __float2bfloat16(v);
}

// tiled transpose + 3-split of x -> (INP, B)
__global__ void split_xt(const float* __restrict__ x) {
    __shared__ float t[32][33];
    const int kb = blockIdx.x * 32, mb = blockIdx.y * 32;
#pragma unroll
    for (int r = 0; r < 32; r += 8) {
        int m = mb + threadIdx.y + r, k = kb + threadIdx.x;
        t[threadIdx.y + r][threadIdx.x] =
            (k < IN_) ? x[(size_t)m * IN_ + k] : 0.0f;
    }
    __syncthreads();
#pragma unroll
    for (int r = 0; r < 32; r += 8) {
        int k = kb + threadIdx.y + r, m = mb + threadIdx.x;
        float v = t[threadIdx.x][threadIdx.y + r];
        size_t o = (size_t)k * B_ + m;
        split3(v, g_xth[o], g_xtm[o], g_xtl[o]);
    }
}

__global__ void prep_w1k(const float* __restrict__ fc1, const float* __restrict__ mask0) {
    int idx = blockIdx.x * blockDim.x + threadIdx.x;
    if (idx >= INP_ * H1_) return;
    int k = idx / H1_, n = idx % H1_;
    float v = (k < IN_) ? fc1[n * IN_ + k] * mask0[k * H1_ + n] : 0.0f;
    split3(v, g_w1kh[idx], g_w1km[idx], g_w1kl[idx]);
}

__global__ void prep_f2k(const float* __restrict__ fc2, const float* __restrict__ mask1,
                         const float* __restrict__ alpha2) {
    int idx = blockIdx.x * blockDim.x + threadIdx.x;
    if (idx >= H1_ * H2_) return;
    int k = idx / H2_, n = idx % H2_;
    float v = fmaf(alpha2[0], g_hb2[idx], fc2[n * H1_ + k] * mask1[idx]);
    split3(v, g_f2kh[idx], g_f2km[idx], g_f2kl[idx]);
}

__global__ void prep_w3(const float* __restrict__ fc3, const float* __restrict__ mask2) {
    int idx = blockIdx.x * blockDim.x + threadIdx.x;
    if (idx >= H2_ * OUT_) return;
    int k = idx / OUT_, n = idx - k * OUT_;
    g_Wm3[idx] = fc3[n * H2_ + k] * mask2[idx];
}

// ---------------------------------------------------------------------------
// Hebb body (R16 tc_hebb arithmetic VERBATIM; smem supplied by caller).
// Hb(M x 1024) = 0.8*Hb + (1-mask)*beta[m]*(d/8192)*(A^T @ P); 64x64, 3-stage.
// ---------------------------------------------------------------------------
template <bool EMIT_AB1>
__device__ __forceinline__ void hebb_body(
    uint32_t smemBase, int hbx,
    const bf16* __restrict__ A, int Mpitch, int M,
    const bf16* __restrict__ P,
    float* __restrict__ Hb, const float* __restrict__ mask,
    const float* __restrict__ beta, float dscale,
    const float* __restrict__ alpha1, bf16* __restrict__ ab1) {
    constexpr uint32_t STG = 32 * 72 * 2;
    const int tid = threadIdx.x, lane = tid & 31, wid = tid >> 5;
    const int wm = wid & 3, wn = wid >> 2;
    const int m0b = (hbx >> 4) * 64, n0b = (hbx & 15) * 64;
    const uint32_t aB0 = smemBase;
    const uint32_t pB0 = smemBase + 3 * STG;

    const int srow = tid >> 3, sc = tid & 7;

    float acc[4][4];
#pragma unroll
    for (int j = 0; j < 4; ++j)
#pragma unroll
        for (int q = 0; q < 4; ++q) acc[j][q] = 0.0f;

    constexpr int V = 8192 / 32;

    auto issue = [&](int c, int s) {
        const bf16* ag = A + (size_t)(c * 32 + srow) * Mpitch + m0b + sc * 8;
        const bf16* pg = P + (size_t)(c * 32 + srow) * 1024 + n0b + sc * 8;
        uint32_t off = (uint32_t)(srow * 72 + sc * 8) * 2 + (uint32_t)s * STG;
        cp16(aB0 + off, ag);
        cp16(pB0 + off, pg);
        cp_commit();
    };

    issue(0, 0);
    issue(1, 1);
    issue(2, 2);
    int s = 0;
    for (int v = 0; v < V; ++v) {
        if (v + 3 <= V) cp_wait<2>();
        else if (v + 2 == V) cp_wait<1>();
        else cp_wait<0>();
        __syncthreads();
        const uint32_t aB = aB0 + (uint32_t)s * STG;
        const uint32_t pB = pB0 + (uint32_t)s * STG;
#pragma unroll
        for (int kk = 0; kk < 2; ++kk) {
            uint32_t af[4];
            {
                int krow = kk * 16 + ((lane >> 4) & 1) * 8 + (lane & 7);
                int mcol = wm * 16 + ((lane >> 3) & 1) * 8;
                ldm_x4_t(af, aB + (uint32_t)(krow * 72 + mcol) * 2);
            }
            uint32_t bf_[4][2];
#pragma unroll
            for (int jj = 0; jj < 2; ++jj) {
                uint32_t r[4];
                int krow = kk * 16 + ((lane >> 3) & 1) * 8 + (lane & 7);
                int ncol = wn * 32 + jj * 16 + ((lane >> 4) & 1) * 8;
                ldm_x4_t(r, pB + (uint32_t)(krow * 72 + ncol) * 2);
                bf_[jj * 2][0] = r[0]; bf_[jj * 2][1] = r[1];
                bf_[jj * 2 + 1][0] = r[2]; bf_[jj * 2 + 1][1] = r[3];
            }
#pragma unroll
            for (int j = 0; j < 4; ++j)
                mma16816(acc[j], af, bf_[j]);
        }
        __syncthreads();
        if (v + 3 < V) issue(v + 3, s);
        s = (s == 2) ? 0 : s + 1;
    }

    const float inv = dscale * (1.0f / 8192.0f);
    const float aV = EMIT_AB1 ? alpha1[0] : 0.0f;
#pragma unroll
    for (int h = 0; h < 2; ++h) {
        const int m = m0b + wm * 16 + (lane >> 2) + h * 8;
        if (m < M) {
            const float bs = beta[m] * inv;
            const size_t roff = (size_t)m * 1024;
#pragma unroll
            for (int j = 0; j < 4; ++j) {
                const int n = n0b + wn * 32 + j * 8 + (lane & 3) * 2;
                const size_t idx = roff + n;
                float2 hb = *reinterpret_cast<const float2*>(Hb + idx);
                float2 mk = *reinterpret_cast<const float2*>(mask + idx);
                hb.x = 0.8f * hb.x + (1.0f - mk.x) * bs * acc[j][h * 2 + 0];
                hb.y = 0.8f * hb.y + (1.0f - mk.y) * bs * acc[j][h * 2 + 1];
                *reinterpret_cast<float2*>(Hb + idx) = hb;
                if (EMIT_AB1) {
                    __nv_bfloat162 av;
                    av.x = __float2bfloat16(aV * hb.x);
                    av.y = __float2bfloat16(aV * hb.y);
                    *reinterpret_cast<__nv_bfloat162*>(ab1 + idx) = av;
                }
            }
        }
    }
}

// ---------------------------------------------------------------------------
// Fused forward + (optional) concurrent hebb kernel.
// 1-D grid: CTAs [0, nHebb) run hebb_body (scheduled FIRST so their long
// K=8192 tails overlap the forward waves); CTAs [nHebb, nHebb+1024) run the
// R16 tcf body (arithmetic VERBATIM -> bitwise-identical results).
// tcf: chunk-outer/product-inner, promotion per 16-k half-chunk, 128x64 tile.
// EP 1: st = acc (C1out = acc); EP 2: st = d*(C1in + acc); EP 3: st = d*acc
// ---------------------------------------------------------------------------
template <int PSET, int EP, bool POST, bool FIRST, bool SPKT,
          bool WITH_HEBB, bool HEB_EMIT>
__global__ void __launch_bounds__(256, 2)
tcff(const bf16* __restrict__ A0, const bf16* __restrict__ A1,
     const bf16* __restrict__ A2,
     const bf16* __restrict__ B0, const bf16* __restrict__ B1,
     const bf16* __restrict__ B2,
     int Kpad, float dscale, const float* __restrict__ eta,
     const float* __restrict__ C1in, float* __restrict__ C1out,
     float* __restrict__ memA, float* __restrict__ spkA,
     bf16* __restrict__ postH, bf16* __restrict__ spkBf,
     bf16* __restrict__ spkT,
     // hebb args
     int nHebb,
     const bf16* __restrict__ hA, int hMpitch, int hM,
     const bf16* __restrict__ hP, float* __restrict__ hHb,
     const float* __restrict__ hMask, const float* __restrict__ hBeta,
     float hD, const float* __restrict__ hAlpha1, bf16* __restrict__ hAb1) {
    extern __shared__ __align__(16) bf16 dyn[];
    const uint32_t smemBase = cvta_smem(&dyn[0]);

    if (WITH_HEBB && (int)blockIdx.x < nHebb) {
        hebb_body<HEB_EMIT>(smemBase, blockIdx.x, hA, hMpitch, hM, hP,
                            hHb, hMask, hBeta, hD, hAlpha1, hAb1);
        return;
    }

    constexpr int NA = (PSET == 0) ? 3 : 1;
    constexpr int NB = (PSET == 1) ? 1 : 3;
    constexpr int CNTa[3] = {NB, (PSET == 0) ? 2 : 0, (PSET == 0) ? 1 : 0};
    constexpr int ST = (PSET == 0) ? 2 : 3;       // pipeline stages
    constexpr uint32_t ATILE = 32 * 136 * 2;      // 8704 B
    constexpr uint32_t BTILE = 32 * 72 * 2;       // 4608 B
    constexpr uint32_t STAGE = NA * ATILE + NB * BTILE;

    const int tid = threadIdx.x, lane = tid & 31, wid = tid >> 5;
    const int wm = wid & 3, wn = wid >> 2;        // 4 x 2 warps (m32 x n32)
    const int t = (int)blockIdx.x - (WITH_HEBB ? nHebb : 0);
    const int bn = t & 15, bm = t >> 4;
    const int KC = Kpad >> 5;

    const bf16* Ap[3] = {A0, A1, A2};
    const bf16* Bp[3] = {B0, B1, B2};

    const int lr = tid >> 3;          // 0..31 (k row within chunk)
    const int lc = tid & 7;           // col group

    float acc[2][4][4];               // mma accumulator (short RZ chains)
    float accM[2][4][4];              // promoted IEEE fp32 accumulator
#pragma unroll
    for (int i = 0; i < 2; ++i)
#pragma unroll
        for (int j = 0; j < 4; ++j)
#pragma unroll
            for (int q = 0; q < 4; ++q) { acc[i][j][q] = 0.0f; accM[i][j][q] = 0.0f; }

    auto issue = [&](int c, int s) {
        const uint32_t base = smemBase + (uint32_t)s * STAGE;
#pragma unroll
        for (int a = 0; a < NA; ++a) {
            const bf16* ag = Ap[a] + (size_t)(c * 32 + lr) * B_ + bm * 128 + lc * 16;
            uint32_t off = base + a * ATILE + (uint32_t)(lr * 136 + lc * 16) * 2;
            cp16(off, ag);
            cp16(off + 16, ag + 8);
        }
#pragma unroll
        for (int b = 0; b < NB; ++b) {
            const bf16* bg = Bp[b] + (size_t)(c * 32 + lr) * 1024 + bn * 64 + lc * 8;
            uint32_t off = base + NA * ATILE + b * BTILE + (uint32_t)(lr * 72 + lc * 8) * 2;
            cp16(off, bg);
        }
        cp_commit();
    };

    issue(0, 0);
    issue(1, 1);
    if (ST == 3) issue(2, 2);
    int s = 0;
    for (int c = 0; c < KC; ++c) {
        if (ST == 2) {
            if (c + 1 < KC) cp_wait<1>(); else cp_wait<0>();
        } else {
            if (c + 2 < KC) cp_wait<2>();
            else if (c + 1 < KC) cp_wait<1>();
            else cp_wait<0>();
        }
        __syncthreads();
        const uint32_t base = smemBase + (uint32_t)s * STAGE;
        const uint32_t bBb = base + NA * ATILE;
#pragma unroll
        for (int kk = 0; kk < 2; ++kk) {
            uint32_t bfr[NB][4][2];
#pragma unroll
            for (int b = 0; b < NB; ++b) {
#pragma unroll
                for (int jj = 0; jj < 2; ++jj) {
                    uint32_t r[4];
                    int krow = kk * 16 + ((lane >> 3) & 1) * 8 + (lane & 7);
                    int ncol = wn * 32 + jj * 16 + ((lane >> 4) & 1) * 8;
                    ldm_x4_t(r, bBb + b * BTILE + (uint32_t)(krow * 72 + ncol) * 2);
                    bfr[b][jj * 2][0] = r[0]; bfr[b][jj * 2][1] = r[1];
                    bfr[b][jj * 2 + 1][0] = r[2]; bfr[b][jj * 2 + 1][1] = r[3];
                }
            }
#pragma unroll
            for (int a = 0; a < NA; ++a) {
                uint32_t af[2][4];
#pragma unroll
                for (int i = 0; i < 2; ++i) {
                    int krow = kk * 16 + ((lane >> 4) & 1) * 8 + (lane & 7);
                    int mcol = wm * 32 + i * 16 + ((lane >> 3) & 1) * 8;
                    ldm_x4_t(af[i], base + a * ATILE + (uint32_t)(krow * 136 + mcol) * 2);
                }
#pragma unroll
                for (int j = 0; j < CNTa[a]; ++j)
#pragma unroll
                    for (int i = 0; i < 2; ++i)
#pragma unroll
                        for (int nt = 0; nt < 4; ++nt)
                            mma16816(acc[i][nt], af[i], bfr[j][nt]);
            }
            // ---- promotion per 16-k half-chunk (R16 order, bitwise) ----
#pragma unroll
            for (int i = 0; i < 2; ++i)
#pragma unroll
                for (int j = 0; j < 4; ++j)
#pragma unroll
                    for (int q = 0; q < 4; ++q) {
                        accM[i][j][q] += acc[i][j][q];
                        acc[i][j][q] = 0.0f;
                    }
        }
        __syncthreads();
        if (c + ST < KC) issue(c + ST, s);
        s = (s + 1 == ST) ? 0 : s + 1;
    }

    // -------- fused SNN epilogue (proven mapping + proven math) --------
    const int mbase = bm * 128 + wm * 32;
    const int nbase = bn * 64 + wn * 32;
#pragma unroll
    for (int i = 0; i < 2; ++i) {
#pragma unroll
        for (int h = 0; h < 2; ++h) {
            const int m = mbase + i * 16 + (lane >> 2) + h * 8;
            const size_t roff = (size_t)m * 1024;
#pragma unroll
            for (int j = 0; j < 4; ++j) {
                const int n = nbase + j * 8 + (lane & 3) * 2;
                const size_t idx = roff + n;
                float c0 = accM[i][j][h * 2 + 0];
                float c1 = accM[i][j][h * 2 + 1];
                float st0, st1;
                if (EP == 1) { st0 = c0; st1 = c1; }
                else if (EP == 2) {
                    float2 cv = *reinterpret_cast<const float2*>(C1in + idx);
                    st0 = dscale * (cv.x + c0);
                    st1 = dscale * (cv.y + c1);
                } else { st0 = dscale * c0; st1 = dscale * c1; }
                float m0v, m1v;
                if (FIRST) { m0v = st0; m1v = st1; }
                else {
                    float2 mv = *reinterpret_cast<const float2*>(memA + idx);
                    float2 sv = *reinterpret_cast<const float2*>(spkA + idx);
                    m0v = (mv.x - sv.x * 0.5f) * 0.8f + st0;
                    m1v = (mv.y - sv.y * 0.5f) * 0.8f + st1;
                }
                float sp0 = ((m0v - 0.5f) > 0.0f) ? 1.0f : 0.0f;
                float sp1 = ((m1v - 0.5f) > 0.0f) ? 1.0f : 0.0f;
                *reinterpret_cast<float2*>(memA + idx) = make_float2(m0v, m1v);
                *reinterpret_cast<float2*>(spkA + idx) = make_float2(sp0, sp1);
                if (EP == 1)
                    *reinterpret_cast<float2*>(C1out + idx) = make_float2(c0, c1);
                if (POST) {
                    float2 ev = *reinterpret_cast<const float2*>(eta + n);
                    float p0 = tanhf(2.0f * m0v - ev.x);
                    float p1 = tanhf(2.0f * m1v - ev.y);
                    __nv_bfloat162 hv;
                    hv.x = __float2bfloat16(p0);
                    hv.y = __float2bfloat16(p1);
                    *reinterpret_cast<__nv_bfloat162*>(postH + idx) = hv;
                }
                if (SPKT) {
                    __nv_bfloat162 sv2;
                    sv2.x = __float2bfloat16(sp0);
                    sv2.y = __float2bfloat16(sp1);
                    *reinterpret_cast<__nv_bfloat162*>(spkBf + idx) = sv2;
                    spkT[(size_t)n * B_ + m]       = sv2.x;
                    spkT[(size_t)(n + 1) * B_ + m] = sv2.y;
                }
            }
        }
    }
}

// ---------------------------------------------------------------------------
// Output GEMM: out(8192 x 10) = m2 @ Wm3   (fp32 SIMT, proven)
// ---------------------------------------------------------------------------
__global__ void __launch_bounds__(256)
out_gemm(const float* __restrict__ m2, const float* __restrict__ Wm3,
         float* __restrict__ out) {
    __shared__ float sW[H2_ * OUT_];
    const int tid = threadIdx.x;
    for (int i = tid; i < H2_ * OUT_; i += blockDim.x) sW[i] = Wm3[i];
    __syncthreads();

    const int warp = tid >> 5, lane = tid & 31;
    const int b = blockIdx.x * 8 + warp;
    const float* row = m2 + (size_t)b * H2_;

    float acc[OUT_];
#pragma unroll
    for (int j = 0; j < OUT_; j++) acc[j] = 0.0f;
    for (int k = lane; k < H2_; k += 32) {
        float v = row[k];
#pragma unroll
        for (int j = 0; j < OUT_; j++) acc[j] = fmaf(v, sW[k * OUT_ + j], acc[j]);
    }
#pragma unroll
    for (int j = 0; j < OUT_; j++) {
        float sv = acc[j];
#pragma unroll
        for (int o = 16; o > 0; o >>= 1) sv += __shfl_xor_sync(0xffffffffu, sv, o);
        if (lane == 0) out[(size_t)b * OUT_ + j] = sv;
    }
}

// ---------------------------------------------------------------------------
extern "C" void kernel_launch(void* const* d_in, const int* in_sizes, int n_in,
                              void* d_out, int out_size) {
    const float* x      = (const float*)d_in[0];
    const float* mask0  = (const float*)d_in[1];
    const float* mask1  = (const float*)d_in[2];
    const float* mask2  = (const float*)d_in[3];
    const float* fc1    = (const float*)d_in[4];
    const float* fc2    = (const float*)d_in[5];
    const float* fc3    = (const float*)d_in[6];
    const float* alpha1 = (const float*)d_in[7];
    const float* alpha2 = (const float*)d_in[8];
    const float* beta1  = (const float*)d_in[9];
    const float* beta2  = (const float*)d_in[10];
    const float* eta1   = (const float*)d_in[11];
    const float* eta2   = (const float*)d_in[12];
    float* out = (float*)d_out;

    bf16 *xh, *xth, *xtm, *xtl, *w1kh, *w1km, *w1kl;
    bf16 *f2kh, *f2km, *f2kl, *ab1h, *s1t, *s1bf, *p1h, *p2h;
    float *Wm3, *C1, *m1, *s1, *m2, *s2, *hb1, *hb2;
    cudaGetSymbolAddress((void**)&xh,   g_xh);
    cudaGetSymbolAddress((void**)&xth,  g_xth);
    cudaGetSymbolAddress((void**)&xtm,  g_xtm);
    cudaGetSymbolAddress((void**)&xtl,  g_xtl);
    cudaGetSymbolAddress((void**)&w1kh, g_w1kh);
    cudaGetSymbolAddress((void**)&w1km, g_w1km);
    cudaGetSymbolAddress((void**)&w1kl, g_w1kl);
    cudaGetSymbolAddress((void**)&f2kh, g_f2kh);
    cudaGetSymbolAddress((void**)&f2km, g_f2km);
    cudaGetSymbolAddress((void**)&f2kl, g_f2kl);
    cudaGetSymbolAddress((void**)&ab1h, g_ab1h);
    cudaGetSymbolAddress((void**)&s1t,  g_s1t);
    cudaGetSymbolAddress((void**)&s1bf, g_s1bf);
    cudaGetSymbolAddress((void**)&p1h,  g_p1h);
    cudaGetSymbolAddress((void**)&p2h,  g_p2h);
    cudaGetSymbolAddress((void**)&Wm3,  g_Wm3);
    cudaGetSymbolAddress((void**)&C1,   g_C1);
    cudaGetSymbolAddress((void**)&m1,   g_m1);
    cudaGetSymbolAddress((void**)&s1,   g_s1);
    cudaGetSymbolAddress((void**)&m2,   g_m2);
    cudaGetSymbolAddress((void**)&s2,   g_s2);
    cudaGetSymbolAddress((void**)&hb1,  g_hb1);
    cudaGetSymbolAddress((void**)&hb2,  g_hb2);

    const float d0 = 1.0f;
    const float d1 = 0.98019867330675525f;   // float32(exp(-1/50))
    const float d2 = 0.96078943915232320f;   // float32(exp(-2/50))

    // dynamic smem sizes
    const int DSM0 = 2 * (3 * 8704 + 3 * 4608);   // 79872 (PSET0, 2-stage)
    const int DSM1 = 3 * (1 * 8704 + 1 * 4608);   // 39936 (PSET1, 3-stage; >= hebb 27648)
    const int DSM2 = 3 * (1 * 8704 + 3 * 4608);   // 67584 (PSET2, 3-stage; >= hebb 27648)

    // instantiations
    auto kC1   = tcff<0, 1, true,  true,  true,  false, false>;  // C1, alone
    auto kL2a  = tcff<2, 3, true,  true,  false, true,  true >;  // tcf2_0 + hebb1_0(emit)
    auto kL1b  = tcff<1, 2, true,  false, true,  true,  false>;  // tcf1_1 + hebb2_0
    auto kL2b  = tcff<2, 3, true,  false, false, true,  true >;  // tcf2_1 + hebb1_1(emit)
    auto kL1c  = tcff<1, 2, false, false, true,  true,  false>;  // tcf1_2 + hebb2_1
    auto kL2c  = tcff<2, 3, false, false, false, false, false>;  // tcf2_2, alone
    cudaFuncSetAttribute(kC1,  cudaFuncAttributeMaxDynamicSharedMemorySize, DSM0);
    cudaFuncSetAttribute(kL2a, cudaFuncAttributeMaxDynamicSharedMemorySize, DSM2);
    cudaFuncSetAttribute(kL1b, cudaFuncAttributeMaxDynamicSharedMemorySize, DSM1);
    cudaFuncSetAttribute(kL2b, cudaFuncAttributeMaxDynamicSharedMemorySize, DSM2);
    cudaFuncSetAttribute(kL1c, cudaFuncAttributeMaxDynamicSharedMemorySize, DSM1);
    cudaFuncSetAttribute(kL2c, cudaFuncAttributeMaxDynamicSharedMemorySize, DSM2);

    // ---- prep ----
    zero_hebb<<<(H1_ * H2_ + 255) / 256, 256>>>();
    split_x<<<(int)(((size_t)B_ * INP_ + 255) / 256), 256>>>(x);
    split_xt<<<dim3(INP_ / 32, B_ / 32), dim3(32, 8)>>>(x);
    prep_w1k<<<(INP_ * H1_ + 255) / 256, 256>>>(fc1, mask0);
    prep_f2k<<<(H1_ * H2_ + 255) / 256, 256>>>(fc2, mask1, alpha2);  // hb2 == 0

    const int nH1 = 16 * 13;    // hebb1 CTAs (64x64 over 784x1024)
    const int nH2 = 16 * 16;    // hebb2 CTAs
    const int nF  = 16 * 64;    // forward CTAs (128x64 over 8192x1024)

    // ---- step 0 ----
    kC1<<<nF, 256, DSM0>>>(
        xth, xtm, xtl, w1kh, w1km, w1kl, INP_, d0, eta1,
        nullptr, C1, m1, s1, p1h, s1bf, s1t,
        0, nullptr, 0, 0, nullptr, nullptr, nullptr, nullptr, 0.f, nullptr, nullptr);
    // tcf2_0 (layer2 step0) || hebb1_0 (emit ab1)
    kL2a<<<nH1 + nF, 256, DSM2>>>(
        s1t, nullptr, nullptr, f2kh, f2km, f2kl, H1_, d0, eta2,
        nullptr, nullptr, m2, s2, p2h, nullptr, nullptr,
        nH1, xh, INP_, IN_, p1h, hb1, mask0, beta1, d0, alpha1, ab1h);
    // tcf1_1 || hebb2_0
    kL1b<<<nH2 + nF, 256, DSM1>>>(
        xth, nullptr, nullptr, ab1h, nullptr, nullptr, INP_, d1, eta1,
        C1, nullptr, m1, s1, p1h, s1bf, s1t,
        nH2, s1bf, H1_, H1_, p2h, hb2, mask1, beta2, d0, nullptr, nullptr);
    prep_f2k<<<(H1_ * H2_ + 255) / 256, 256>>>(fc2, mask1, alpha2);
    // tcf2_1 || hebb1_1 (emit ab1)
    kL2b<<<nH1 + nF, 256, DSM2>>>(
        s1t, nullptr, nullptr, f2kh, f2km, f2kl, H1_, d1, eta2,
        nullptr, nullptr, m2, s2, p2h, nullptr, nullptr,
        nH1, xh, INP_, IN_, p1h, hb1, mask0, beta1, d1, alpha1, ab1h);
    // tcf1_2 || hebb2_1
    kL1c<<<nH2 + nF, 256, DSM1>>>(
        xth, nullptr, nullptr, ab1h, nullptr, nullptr, INP_, d2, eta1,
        C1, nullptr, m1, s1, nullptr, s1bf, s1t,
        nH2, s1bf, H1_, H1_, p2h, hb2, mask1, beta2, d1, nullptr, nullptr);
    prep_f2k<<<(H1_ * H2_ + 255) / 256, 256>>>(fc2, mask1, alpha2);
    // tcf2_2 alone (final hebb updates skipped: never consumed)
    kL2c<<<nF, 256, DSM2>>>(
        s1t, nullptr, nullptr, f2kh, f2km, f2kl, H1_, d2, eta2,
        nullptr, nullptr, m2, s2, nullptr, nullptr, nullptr,
        0, nullptr, 0, 0, nullptr, nullptr, nullptr, nullptr, 0.f, nullptr, nullptr);

    // ---- output ----
    prep_w3<<<(H2_ * OUT_ + 255) / 256, 256>>>(fc3, mask2);
    out_gemm<<<B_ / 8, 256>>>(m2, Wm3, out);
}